// round 2
// baseline (speedup 1.0000x reference)
#include <cuda_runtime.h>
#include <math.h>
#include <float.h>

// Problem dims (fixed by the dataset problem)
#define Bn 4
#define Pn 64
#define Dn 768
#define Nn 2048
#define Rn 12
#define Kn 16
#define Mn (Bn * Pn)   // 256 query rows

// Scratch (device globals — no allocation allowed)
__device__ float g_keys[Nn * Dn];     // normalized keys  (6 MB)
__device__ float g_asum[Nn * Nn];     // sum over R of adjacency (16 MB)
__device__ float g_scores[Mn * Nn];   // (2 MB)
__device__ float g_w[Mn * Kn];
__device__ int   g_idx[Mn * Kn];
__device__ float g_nei[Mn * Nn];      // (2 MB)

// ---------------------------------------------------------------------------
// Kernel 1: row-normalize keys_param -> g_keys
// grid 2048 blocks x 256 threads; each block handles one row of 768 floats.
// ---------------------------------------------------------------------------
__global__ __launch_bounds__(256) void k_norm(const float* __restrict__ kp) {
    int n   = blockIdx.x;
    int tid = threadIdx.x;
    const float* row = kp + (size_t)n * Dn;

    float v0 = row[tid];
    float v1 = row[tid + 256];
    float v2 = row[tid + 512];
    float s  = v0 * v0 + v1 * v1 + v2 * v2;

    #pragma unroll
    for (int o = 16; o; o >>= 1) s += __shfl_xor_sync(0xffffffffu, s, o);

    __shared__ float red[8];
    __shared__ float sinv;
    if ((tid & 31) == 0) red[tid >> 5] = s;
    __syncthreads();
    if (tid == 0) {
        float t = 0.f;
        #pragma unroll
        for (int i = 0; i < 8; i++) t += red[i];
        sinv = rsqrtf(t + 1e-12f);
    }
    __syncthreads();
    float inv = sinv;
    float* out = g_keys + (size_t)n * Dn;
    out[tid]       = v0 * inv;
    out[tid + 256] = v1 * inv;
    out[tid + 512] = v2 * inv;
}

// ---------------------------------------------------------------------------
// Kernel 2: A_sum = sum over r of adjacency[r]  (reads 192 MB — the roofline)
// 4096 blocks x 256 threads, one float4 per thread.
// ---------------------------------------------------------------------------
__global__ __launch_bounds__(256) void k_asum(const float4* __restrict__ adj) {
    size_t i = (size_t)blockIdx.x * blockDim.x + threadIdx.x;  // 0..1048575
    float4 s = adj[i];
    #pragma unroll
    for (int r = 1; r < Rn; r++) {
        float4 t = adj[i + (size_t)r * (Nn * Nn / 4)];
        s.x += t.x; s.y += t.y; s.z += t.z; s.w += t.w;
    }
    ((float4*)g_asum)[i] = s;
}

// ---------------------------------------------------------------------------
// Kernel 3: scores = positions (256x768) @ keys^T (2048x768)  [NT SGEMM]
// BM=64, BN=64, BK=16, 256 threads, 4x4 per thread. Grid (32, 4).
// ---------------------------------------------------------------------------
__global__ __launch_bounds__(256) void k_scores(const float* __restrict__ A) {
    const int BM = 64, BN = 64, BK = 16;
    __shared__ float As[BK][BM + 4];
    __shared__ float Bs[BK][BN + 4];

    int tid = threadIdx.x;
    int m0 = blockIdx.y * BM;
    int n0 = blockIdx.x * BN;

    int lr = tid >> 2;          // 0..63 (row within tile for loads)
    int lk = (tid & 3) * 4;     // 0,4,8,12 (k offset for loads)
    int rm = (tid >> 4) * 4;    // 0..60
    int rn = (tid & 15) * 4;    // 0..60

    float acc[4][4];
    #pragma unroll
    for (int i = 0; i < 4; i++)
        #pragma unroll
        for (int j = 0; j < 4; j++) acc[i][j] = 0.f;

    for (int kb = 0; kb < Dn; kb += BK) {
        float4 a = *(const float4*)&A[(size_t)(m0 + lr) * Dn + kb + lk];
        float4 b = *(const float4*)&g_keys[(size_t)(n0 + lr) * Dn + kb + lk];
        As[lk + 0][lr] = a.x; As[lk + 1][lr] = a.y;
        As[lk + 2][lr] = a.z; As[lk + 3][lr] = a.w;
        Bs[lk + 0][lr] = b.x; Bs[lk + 1][lr] = b.y;
        Bs[lk + 2][lr] = b.z; Bs[lk + 3][lr] = b.w;
        __syncthreads();

        #pragma unroll
        for (int kk = 0; kk < BK; kk++) {
            float4 ra = *(float4*)&As[kk][rm];
            float4 rb = *(float4*)&Bs[kk][rn];
            acc[0][0] += ra.x * rb.x; acc[0][1] += ra.x * rb.y;
            acc[0][2] += ra.x * rb.z; acc[0][3] += ra.x * rb.w;
            acc[1][0] += ra.y * rb.x; acc[1][1] += ra.y * rb.y;
            acc[1][2] += ra.y * rb.z; acc[1][3] += ra.y * rb.w;
            acc[2][0] += ra.z * rb.x; acc[2][1] += ra.z * rb.y;
            acc[2][2] += ra.z * rb.z; acc[2][3] += ra.z * rb.w;
            acc[3][0] += ra.w * rb.x; acc[3][1] += ra.w * rb.y;
            acc[3][2] += ra.w * rb.z; acc[3][3] += ra.w * rb.w;
        }
        __syncthreads();
    }

    #pragma unroll
    for (int i = 0; i < 4; i++) {
        float4 v = make_float4(acc[i][0], acc[i][1], acc[i][2], acc[i][3]);
        *(float4*)&g_scores[(size_t)(m0 + rm + i) * Nn + n0 + rn] = v;
    }
}

// ---------------------------------------------------------------------------
// Kernel 4: per-row top-16 (value desc, tie -> lower index) + softmax
// 256 blocks x 256 threads; scores row cached in smem; 16 x block-argmax.
// ---------------------------------------------------------------------------
__global__ __launch_bounds__(256) void k_topk() {
    __shared__ float s[Nn];
    __shared__ float bv[256];
    __shared__ int   bi[256];
    __shared__ float tv[Kn];
    __shared__ int   ti[Kn];
    __shared__ float ssum;

    int m = blockIdx.x, tid = threadIdx.x;
    const float* row = g_scores + (size_t)m * Nn;
    for (int j = tid; j < Nn; j += 256) s[j] = row[j];
    __syncthreads();

    for (int it = 0; it < Kn; it++) {
        float best = -FLT_MAX; int besti = 0;
        for (int j = tid; j < Nn; j += 256) {
            float v = s[j];
            if (v > best) { best = v; besti = j; }
        }
        bv[tid] = best; bi[tid] = besti;
        __syncthreads();
        #pragma unroll
        for (int o = 128; o; o >>= 1) {
            if (tid < o) {
                float vo = bv[tid + o]; int io = bi[tid + o];
                if (vo > bv[tid] || (vo == bv[tid] && io < bi[tid])) {
                    bv[tid] = vo; bi[tid] = io;
                }
            }
            __syncthreads();
        }
        if (tid == 0) {
            tv[it] = bv[0]; ti[it] = bi[0];
            s[bi[0]] = -FLT_MAX;
        }
        __syncthreads();
    }

    if (tid == 0) {
        float mx = tv[0], sum = 0.f;
        #pragma unroll
        for (int i = 0; i < Kn; i++) sum += expf(tv[i] - mx);
        ssum = sum;
    }
    __syncthreads();
    if (tid < Kn) {
        g_w[m * Kn + tid]   = expf(tv[tid] - tv[0]) / ssum;
        g_idx[m * Kn + tid] = ti[tid];
    }
}

// ---------------------------------------------------------------------------
// Kernel 5: nei[m,:] = sum_k w[m,k] * A_sum[idx[m,k], :]
// 256 blocks x 256 threads, float4 columns (A_sum rows hit L2).
// ---------------------------------------------------------------------------
__global__ __launch_bounds__(256) void k_gather() {
    int m = blockIdx.x, tid = threadIdx.x;
    __shared__ float ws[Kn];
    __shared__ int   is[Kn];
    if (tid < Kn) { ws[tid] = g_w[m * Kn + tid]; is[tid] = g_idx[m * Kn + tid]; }
    __syncthreads();

    for (int c = tid; c < Nn / 4; c += 256) {
        float4 acc = make_float4(0.f, 0.f, 0.f, 0.f);
        #pragma unroll
        for (int k = 0; k < Kn; k++) {
            const float4 v = ((const float4*)(g_asum + (size_t)is[k] * Nn))[c];
            float wk = ws[k];
            acc.x += wk * v.x; acc.y += wk * v.y;
            acc.z += wk * v.z; acc.w += wk * v.w;
        }
        ((float4*)(g_nei + (size_t)m * Nn))[c] = acc;
    }
}

// ---------------------------------------------------------------------------
// Kernel 6: out = nei (256x2048) @ keys (2048x768)  [NN SGEMM]
// BM=32, BN=64, BK=32, 256 threads, 2x4 per thread. Grid (12, 8).
// ---------------------------------------------------------------------------
__global__ __launch_bounds__(256) void k_out(float* __restrict__ C) {
    const int BM = 32, BN = 64, BK = 32;
    __shared__ float As[BK][BM + 4];
    __shared__ float Bs[BK][BN];

    int tid = threadIdx.x;
    int m0 = blockIdx.y * BM;
    int n0 = blockIdx.x * BN;

    int ar = tid >> 3;          // 0..31
    int ak = (tid & 7) * 4;     // 0..28
    int br = tid >> 4;          // 0..15 (loads rows br and br+16)
    int bc = (tid & 15) * 4;    // 0..60
    int rm = (tid >> 4) * 2;    // 0..30
    int rn = (tid & 15) * 4;    // 0..60

    float acc[2][4];
    #pragma unroll
    for (int i = 0; i < 2; i++)
        #pragma unroll
        for (int j = 0; j < 4; j++) acc[i][j] = 0.f;

    for (int kb = 0; kb < Nn; kb += BK) {
        float4 a = *(const float4*)&g_nei[(size_t)(m0 + ar) * Nn + kb + ak];
        As[ak + 0][ar] = a.x; As[ak + 1][ar] = a.y;
        As[ak + 2][ar] = a.z; As[ak + 3][ar] = a.w;
        float4 b0 = *(const float4*)&g_keys[(size_t)(kb + br) * Dn + n0 + bc];
        float4 b1 = *(const float4*)&g_keys[(size_t)(kb + br + 16) * Dn + n0 + bc];
        *(float4*)&Bs[br][bc]      = b0;
        *(float4*)&Bs[br + 16][bc] = b1;
        __syncthreads();

        #pragma unroll
        for (int kk = 0; kk < BK; kk++) {
            float a0 = As[kk][rm], a1 = As[kk][rm + 1];
            float4 rb = *(float4*)&Bs[kk][rn];
            acc[0][0] += a0 * rb.x; acc[0][1] += a0 * rb.y;
            acc[0][2] += a0 * rb.z; acc[0][3] += a0 * rb.w;
            acc[1][0] += a1 * rb.x; acc[1][1] += a1 * rb.y;
            acc[1][2] += a1 * rb.z; acc[1][3] += a1 * rb.w;
        }
        __syncthreads();
    }

    #pragma unroll
    for (int i = 0; i < 2; i++) {
        float4 v = make_float4(acc[i][0], acc[i][1], acc[i][2], acc[i][3]);
        *(float4*)&C[(size_t)(m0 + rm + i) * Dn + n0 + rn] = v;
    }
}

// ---------------------------------------------------------------------------
// Host launcher — all launches on the default stream (graph-capturable).
// Input order per metadata: positions, keys_param, adjacency, k (ignored; k=16).
// ---------------------------------------------------------------------------
extern "C" void kernel_launch(void* const* d_in, const int* in_sizes, int n_in,
                              void* d_out, int out_size) {
    (void)in_sizes; (void)n_in; (void)out_size;
    const float* positions = (const float*)d_in[0];
    const float* keys_p    = (const float*)d_in[1];
    const float* adjacency = (const float*)d_in[2];
    float* out = (float*)d_out;

    k_norm  <<<Nn, 256>>>(keys_p);
    k_asum  <<<(Nn * Nn / 4) / 256, 256>>>((const float4*)adjacency);
    k_scores<<<dim3(Nn / 64, Mn / 64), 256>>>(positions);
    k_topk  <<<Mn, 256>>>();
    k_gather<<<Mn, 256>>>();
    k_out   <<<dim3(Dn / 64, Mn / 32), 256>>>(out);
}

// round 3
// speedup vs baseline: 1.2961x; 1.2961x over previous
#include <cuda_runtime.h>
#include <math.h>
#include <float.h>

// Problem dims (fixed by the dataset problem)
#define Bn 4
#define Pn 64
#define Dn 768
#define Nn 2048
#define Rn 12
#define Kn 16
#define Mn (Bn * Pn)   // 256 query rows
#define SPLITK 4       // split-K factor for k_out

// Scratch (device globals — no allocation allowed)
__device__ float g_keys[Nn * Dn];          // normalized keys  (6 MB)
__device__ float g_asum[Nn * Nn];          // sum over R of adjacency (16 MB)
__device__ float g_scores[Mn * Nn];        // (2 MB)
__device__ float g_w[Mn * Kn];
__device__ int   g_idx[Mn * Kn];
__device__ float g_nei[Mn * Nn];           // (2 MB)
__device__ float g_outp[SPLITK][Mn * Dn];  // split-K partials (3 MB)

// ---------------------------------------------------------------------------
// Kernel 1: row-normalize keys_param -> g_keys
// ---------------------------------------------------------------------------
__global__ __launch_bounds__(256) void k_norm(const float* __restrict__ kp) {
    int n   = blockIdx.x;
    int tid = threadIdx.x;
    const float* row = kp + (size_t)n * Dn;

    float v0 = row[tid];
    float v1 = row[tid + 256];
    float v2 = row[tid + 512];
    float s  = v0 * v0 + v1 * v1 + v2 * v2;

    #pragma unroll
    for (int o = 16; o; o >>= 1) s += __shfl_xor_sync(0xffffffffu, s, o);

    __shared__ float red[8];
    __shared__ float sinv;
    if ((tid & 31) == 0) red[tid >> 5] = s;
    __syncthreads();
    if (tid == 0) {
        float t = 0.f;
        #pragma unroll
        for (int i = 0; i < 8; i++) t += red[i];
        sinv = rsqrtf(t + 1e-12f);
    }
    __syncthreads();
    float inv = sinv;
    float* out = g_keys + (size_t)n * Dn;
    out[tid]       = v0 * inv;
    out[tid + 256] = v1 * inv;
    out[tid + 512] = v2 * inv;
}

// ---------------------------------------------------------------------------
// Kernel 2: A_sum = sum over r of adjacency[r]  (192 MB stream — HBM floor)
// ---------------------------------------------------------------------------
__global__ __launch_bounds__(256) void k_asum(const float4* __restrict__ adj) {
    size_t i = (size_t)blockIdx.x * blockDim.x + threadIdx.x;
    float4 s = adj[i];
    #pragma unroll
    for (int r = 1; r < Rn; r++) {
        float4 t = adj[i + (size_t)r * (Nn * Nn / 4)];
        s.x += t.x; s.y += t.y; s.z += t.z; s.w += t.w;
    }
    ((float4*)g_asum)[i] = s;
}

// ---------------------------------------------------------------------------
// Kernel 3: scores = positions (256x768) @ keys^T (2048x768)  [NT SGEMM]
// BM=64, BN=64, BK=16, 256 threads, 4x4 per thread. Grid (32, 4).
// ---------------------------------------------------------------------------
__global__ __launch_bounds__(256) void k_scores(const float* __restrict__ A) {
    const int BM = 64, BN = 64, BK = 16;
    __shared__ float As[BK][BM + 4];
    __shared__ float Bs[BK][BN + 4];

    int tid = threadIdx.x;
    int m0 = blockIdx.y * BM;
    int n0 = blockIdx.x * BN;

    int lr = tid >> 2;          // 0..63
    int lk = (tid & 3) * 4;     // 0,4,8,12
    int rm = (tid >> 4) * 4;    // 0..60
    int rn = (tid & 15) * 4;    // 0..60

    float acc[4][4];
    #pragma unroll
    for (int i = 0; i < 4; i++)
        #pragma unroll
        for (int j = 0; j < 4; j++) acc[i][j] = 0.f;

    for (int kb = 0; kb < Dn; kb += BK) {
        float4 a = *(const float4*)&A[(size_t)(m0 + lr) * Dn + kb + lk];
        float4 b = *(const float4*)&g_keys[(size_t)(n0 + lr) * Dn + kb + lk];
        As[lk + 0][lr] = a.x; As[lk + 1][lr] = a.y;
        As[lk + 2][lr] = a.z; As[lk + 3][lr] = a.w;
        Bs[lk + 0][lr] = b.x; Bs[lk + 1][lr] = b.y;
        Bs[lk + 2][lr] = b.z; Bs[lk + 3][lr] = b.w;
        __syncthreads();

        #pragma unroll
        for (int kk = 0; kk < BK; kk++) {
            float4 ra = *(float4*)&As[kk][rm];
            float4 rb = *(float4*)&Bs[kk][rn];
            acc[0][0] += ra.x * rb.x; acc[0][1] += ra.x * rb.y;
            acc[0][2] += ra.x * rb.z; acc[0][3] += ra.x * rb.w;
            acc[1][0] += ra.y * rb.x; acc[1][1] += ra.y * rb.y;
            acc[1][2] += ra.y * rb.z; acc[1][3] += ra.y * rb.w;
            acc[2][0] += ra.z * rb.x; acc[2][1] += ra.z * rb.y;
            acc[2][2] += ra.z * rb.z; acc[2][3] += ra.z * rb.w;
            acc[3][0] += ra.w * rb.x; acc[3][1] += ra.w * rb.y;
            acc[3][2] += ra.w * rb.z; acc[3][3] += ra.w * rb.w;
        }
        __syncthreads();
    }

    #pragma unroll
    for (int i = 0; i < 4; i++) {
        float4 v = make_float4(acc[i][0], acc[i][1], acc[i][2], acc[i][3]);
        *(float4*)&g_scores[(size_t)(m0 + rm + i) * Nn + n0 + rn] = v;
    }
}

// ---------------------------------------------------------------------------
// Kernel 4: per-row top-16 + softmax.  Register-resident values, 2 barriers
// per iteration (was 9).  Tie-break: value desc, lower index wins.
// ---------------------------------------------------------------------------
__global__ __launch_bounds__(256) void k_topk() {
    __shared__ float wv[8];
    __shared__ int   wi[8];
    __shared__ float bcv;   // broadcast winner value (unused by readers, kept for clarity)
    __shared__ int   bci;   // broadcast winner index
    __shared__ float tv[Kn];
    __shared__ int   ti[Kn];
    __shared__ float ssum;

    int m = blockIdx.x, tid = threadIdx.x;
    int lane = tid & 31, warp = tid >> 5;
    const float* row = g_scores + (size_t)m * Nn;

    float v[8];
    #pragma unroll
    for (int j = 0; j < 8; j++) v[j] = row[j * 256 + tid];   // coalesced

    for (int it = 0; it < Kn; it++) {
        // local argmax over 8 register values (ascending j -> lowest index on tie)
        float best = v[0]; int bj = 0;
        #pragma unroll
        for (int j = 1; j < 8; j++) if (v[j] > best) { best = v[j]; bj = j; }
        int bidx = bj * 256 + tid;

        // warp argmax via shfl (value desc, lower index on tie)
        #pragma unroll
        for (int o = 16; o; o >>= 1) {
            float ov = __shfl_xor_sync(0xffffffffu, best, o);
            int   oi = __shfl_xor_sync(0xffffffffu, bidx, o);
            if (ov > best || (ov == best && oi < bidx)) { best = ov; bidx = oi; }
        }
        if (lane == 0) { wv[warp] = best; wi[warp] = bidx; }
        __syncthreads();

        if (tid == 0) {
            float b = wv[0]; int bi2 = wi[0];
            #pragma unroll
            for (int w = 1; w < 8; w++)
                if (wv[w] > b || (wv[w] == b && wi[w] < bi2)) { b = wv[w]; bi2 = wi[w]; }
            bcv = b; bci = bi2;
            tv[it] = b; ti[it] = bi2;
        }
        __syncthreads();

        int ki = bci;
        if ((ki & 255) == tid) v[ki >> 8] = -FLT_MAX;   // kill winner locally
    }

    if (tid == 0) {
        float mx = tv[0], sum = 0.f;
        #pragma unroll
        for (int i = 0; i < Kn; i++) sum += expf(tv[i] - mx);
        ssum = sum;
    }
    __syncthreads();
    if (tid < Kn) {
        g_w[m * Kn + tid]   = expf(tv[tid] - tv[0]) / ssum;
        g_idx[m * Kn + tid] = ti[tid];
    }
}

// ---------------------------------------------------------------------------
// Kernel 5: nei[m,:] = sum_k w[m,k] * A_sum[idx[m,k], :]
// ---------------------------------------------------------------------------
__global__ __launch_bounds__(256) void k_gather() {
    int m = blockIdx.x, tid = threadIdx.x;
    __shared__ float ws[Kn];
    __shared__ int   is[Kn];
    if (tid < Kn) { ws[tid] = g_w[m * Kn + tid]; is[tid] = g_idx[m * Kn + tid]; }
    __syncthreads();

    for (int c = tid; c < Nn / 4; c += 256) {
        float4 acc = make_float4(0.f, 0.f, 0.f, 0.f);
        #pragma unroll
        for (int k = 0; k < Kn; k++) {
            const float4 v = ((const float4*)(g_asum + (size_t)is[k] * Nn))[c];
            float wk = ws[k];
            acc.x += wk * v.x; acc.y += wk * v.y;
            acc.z += wk * v.z; acc.w += wk * v.w;
        }
        ((float4*)(g_nei + (size_t)m * Nn))[c] = acc;
    }
}

// ---------------------------------------------------------------------------
// Kernel 6: out = nei (256x2048) @ keys (2048x768)  [NN SGEMM, split-K]
// BM=64, BN=64, BK=16, 4x4/thread.  Grid (12, 4, SPLITK) = 192 blocks.
// Each z-slice accumulates over K chunk of 512 into its partial buffer.
// ---------------------------------------------------------------------------
__global__ __launch_bounds__(256) void k_out() {
    const int BM = 64, BN = 64, BK = 16;
    const int KC = Nn / SPLITK;   // 512
    __shared__ float As[BK][BM + 4];
    __shared__ float Bs[BK][BN + 4];

    int tid = threadIdx.x;
    int m0 = blockIdx.y * BM;
    int n0 = blockIdx.x * BN;
    int kbase = blockIdx.z * KC;

    int lr = tid >> 2;          // 0..63 (A row)
    int lk = (tid & 3) * 4;     // 0,4,8,12 (A k-offset)
    int br = tid >> 4;          // 0..15 (B k-row)
    int bc = (tid & 15) * 4;    // 0..60 (B col)
    int rm = (tid >> 4) * 4;
    int rn = (tid & 15) * 4;

    float acc[4][4];
    #pragma unroll
    for (int i = 0; i < 4; i++)
        #pragma unroll
        for (int j = 0; j < 4; j++) acc[i][j] = 0.f;

    for (int kb = kbase; kb < kbase + KC; kb += BK) {
        float4 a = *(const float4*)&g_nei[(size_t)(m0 + lr) * Nn + kb + lk];
        As[lk + 0][lr] = a.x; As[lk + 1][lr] = a.y;
        As[lk + 2][lr] = a.z; As[lk + 3][lr] = a.w;
        float4 b = *(const float4*)&g_keys[(size_t)(kb + br) * Dn + n0 + bc];
        *(float4*)&Bs[br][bc] = b;
        __syncthreads();

        #pragma unroll
        for (int kk = 0; kk < BK; kk++) {
            float4 ra = *(float4*)&As[kk][rm];
            float4 rb = *(float4*)&Bs[kk][rn];
            acc[0][0] += ra.x * rb.x; acc[0][1] += ra.x * rb.y;
            acc[0][2] += ra.x * rb.z; acc[0][3] += ra.x * rb.w;
            acc[1][0] += ra.y * rb.x; acc[1][1] += ra.y * rb.y;
            acc[1][2] += ra.y * rb.z; acc[1][3] += ra.y * rb.w;
            acc[2][0] += ra.z * rb.x; acc[2][1] += ra.z * rb.y;
            acc[2][2] += ra.z * rb.z; acc[2][3] += ra.z * rb.w;
            acc[3][0] += ra.w * rb.x; acc[3][1] += ra.w * rb.y;
            acc[3][2] += ra.w * rb.z; acc[3][3] += ra.w * rb.w;
        }
        __syncthreads();
    }

    float* P = g_outp[blockIdx.z];
    #pragma unroll
    for (int i = 0; i < 4; i++) {
        float4 v = make_float4(acc[i][0], acc[i][1], acc[i][2], acc[i][3]);
        *(float4*)&P[(size_t)(m0 + rm + i) * Dn + n0 + rn] = v;
    }
}

// ---------------------------------------------------------------------------
// Kernel 7: out = sum of SPLITK partials (also initializes poisoned d_out)
// ---------------------------------------------------------------------------
__global__ __launch_bounds__(256) void k_reduce(float4* __restrict__ out) {
    int i = blockIdx.x * 256 + threadIdx.x;   // 0 .. Mn*Dn/4-1
    float4 r = ((const float4*)g_outp[0])[i];
    #pragma unroll
    for (int s = 1; s < SPLITK; s++) {
        float4 t = ((const float4*)g_outp[s])[i];
        r.x += t.x; r.y += t.y; r.z += t.z; r.w += t.w;
    }
    out[i] = r;
}

// ---------------------------------------------------------------------------
// Host launcher — default stream, graph-capturable.
// Inputs: positions, keys_param, adjacency, k (fixed 16).
// ---------------------------------------------------------------------------
extern "C" void kernel_launch(void* const* d_in, const int* in_sizes, int n_in,
                              void* d_out, int out_size) {
    (void)in_sizes; (void)n_in; (void)out_size;
    const float* positions = (const float*)d_in[0];
    const float* keys_p    = (const float*)d_in[1];
    const float* adjacency = (const float*)d_in[2];
    float* out = (float*)d_out;

    k_norm  <<<Nn, 256>>>(keys_p);
    k_asum  <<<(Nn * Nn / 4) / 256, 256>>>((const float4*)adjacency);
    k_scores<<<dim3(Nn / 64, Mn / 64), 256>>>(positions);
    k_topk  <<<Mn, 256>>>();
    k_gather<<<Mn, 256>>>();
    k_out   <<<dim3(Dn / 64, Mn / 64, SPLITK), 256>>>();
    k_reduce<<<(Mn * Dn / 4) / 256, 256>>>((float4*)out);
}

// round 4
// speedup vs baseline: 1.4809x; 1.1426x over previous
#include <cuda_runtime.h>
#include <math.h>
#include <float.h>

// Problem dims (fixed by the dataset problem)
#define Bn 4
#define Pn 64
#define Dn 768
#define Nn 2048
#define Rn 12
#define Kn 16
#define Mn (Bn * Pn)   // 256 query rows
#define SPLITK 4       // split-K factor for k_out

// Scratch (device globals — no allocation allowed)
__device__ float g_keys[Nn * Dn];          // normalized keys  (6 MB)
__device__ float g_asum[Nn * Nn];          // sum over R of adjacency (16 MB)
__device__ float g_scores[Mn * Nn];        // (2 MB)
__device__ float g_w[Mn * Kn];
__device__ int   g_idx[Mn * Kn];
__device__ float g_nei[Mn * Nn];           // (2 MB)
__device__ float g_outp[SPLITK][Mn * Dn];  // split-K partials (3 MB)

// ---------------------------------------------------------------------------
// Kernel 1: row-normalize keys_param -> g_keys
// ---------------------------------------------------------------------------
__global__ __launch_bounds__(256) void k_norm(const float* __restrict__ kp) {
    int n   = blockIdx.x;
    int tid = threadIdx.x;
    const float* row = kp + (size_t)n * Dn;

    float v0 = row[tid];
    float v1 = row[tid + 256];
    float v2 = row[tid + 512];
    float s  = v0 * v0 + v1 * v1 + v2 * v2;

    #pragma unroll
    for (int o = 16; o; o >>= 1) s += __shfl_xor_sync(0xffffffffu, s, o);

    __shared__ float red[8];
    __shared__ float sinv;
    if ((tid & 31) == 0) red[tid >> 5] = s;
    __syncthreads();
    if (tid == 0) {
        float t = 0.f;
        #pragma unroll
        for (int i = 0; i < 8; i++) t += red[i];
        sinv = rsqrtf(t + 1e-12f);
    }
    __syncthreads();
    float inv = sinv;
    float* out = g_keys + (size_t)n * Dn;
    out[tid]       = v0 * inv;
    out[tid + 256] = v1 * inv;
    out[tid + 512] = v2 * inv;
}

// ---------------------------------------------------------------------------
// Kernel 2: A_sum = sum over r of adjacency[r]  (192 MB stream — HBM floor)
// ---------------------------------------------------------------------------
__global__ __launch_bounds__(256) void k_asum(const float4* __restrict__ adj) {
    size_t i = (size_t)blockIdx.x * blockDim.x + threadIdx.x;
    float4 s = adj[i];
    #pragma unroll
    for (int r = 1; r < Rn; r++) {
        float4 t = adj[i + (size_t)r * (Nn * Nn / 4)];
        s.x += t.x; s.y += t.y; s.z += t.z; s.w += t.w;
    }
    ((float4*)g_asum)[i] = s;
}

// ---------------------------------------------------------------------------
// Kernel 3: scores = positions (256x768) @ keys^T (2048x768)  [NT SGEMM]
// BM=64, BN=64, BK=16, 256 threads, 4x4/thread, register double buffering.
// ---------------------------------------------------------------------------
__global__ __launch_bounds__(256) void k_scores(const float* __restrict__ A) {
    const int BM = 64, BN = 64, BK = 16;
    __shared__ float As[BK][BM + 4];
    __shared__ float Bs[BK][BN + 4];

    int tid = threadIdx.x;
    int m0 = blockIdx.y * BM;
    int n0 = blockIdx.x * BN;

    int lr = tid >> 2;          // 0..63
    int lk = (tid & 3) * 4;     // 0,4,8,12
    int rm = (tid >> 4) * 4;    // 0..60
    int rn = (tid & 15) * 4;    // 0..60

    float acc[4][4];
    #pragma unroll
    for (int i = 0; i < 4; i++)
        #pragma unroll
        for (int j = 0; j < 4; j++) acc[i][j] = 0.f;

    // prologue: fetch first tile into registers
    float4 a = *(const float4*)&A[(size_t)(m0 + lr) * Dn + lk];
    float4 b = *(const float4*)&g_keys[(size_t)(n0 + lr) * Dn + lk];

    for (int kb = 0; kb < Dn; kb += BK) {
        As[lk + 0][lr] = a.x; As[lk + 1][lr] = a.y;
        As[lk + 2][lr] = a.z; As[lk + 3][lr] = a.w;
        Bs[lk + 0][lr] = b.x; Bs[lk + 1][lr] = b.y;
        Bs[lk + 2][lr] = b.z; Bs[lk + 3][lr] = b.w;
        __syncthreads();

        // prefetch next tile (in flight during compute below)
        if (kb + BK < Dn) {
            a = *(const float4*)&A[(size_t)(m0 + lr) * Dn + kb + BK + lk];
            b = *(const float4*)&g_keys[(size_t)(n0 + lr) * Dn + kb + BK + lk];
        }

        #pragma unroll
        for (int kk = 0; kk < BK; kk++) {
            float4 ra = *(float4*)&As[kk][rm];
            float4 rb = *(float4*)&Bs[kk][rn];
            acc[0][0] += ra.x * rb.x; acc[0][1] += ra.x * rb.y;
            acc[0][2] += ra.x * rb.z; acc[0][3] += ra.x * rb.w;
            acc[1][0] += ra.y * rb.x; acc[1][1] += ra.y * rb.y;
            acc[1][2] += ra.y * rb.z; acc[1][3] += ra.y * rb.w;
            acc[2][0] += ra.z * rb.x; acc[2][1] += ra.z * rb.y;
            acc[2][2] += ra.z * rb.z; acc[2][3] += ra.z * rb.w;
            acc[3][0] += ra.w * rb.x; acc[3][1] += ra.w * rb.y;
            acc[3][2] += ra.w * rb.z; acc[3][3] += ra.w * rb.w;
        }
        __syncthreads();
    }

    #pragma unroll
    for (int i = 0; i < 4; i++) {
        float4 v = make_float4(acc[i][0], acc[i][1], acc[i][2], acc[i][3]);
        *(float4*)&g_scores[(size_t)(m0 + rm + i) * Nn + n0 + rn] = v;
    }
}

// ---------------------------------------------------------------------------
// Kernel 4: per-row top-16 + softmax.  ONE WARP PER ROW — no block barriers.
// 64 values/lane in registers, 64-bit kill mask, shfl argmax per iteration.
// Tie-break: value desc, lower index wins (matches lax.top_k).
// ---------------------------------------------------------------------------
__global__ __launch_bounds__(128) void k_topk() {
    int warp = blockIdx.x * 4 + (threadIdx.x >> 5);   // row id 0..255
    int lane = threadIdx.x & 31;
    const float* row = g_scores + (size_t)warp * Nn;

    float v[64];
    #pragma unroll
    for (int j = 0; j < 64; j++) v[j] = row[j * 32 + lane];   // coalesced

    unsigned long long kill = 0ULL;

    __shared__ float tv_s[4][Kn];
    __shared__ int   ti_s[4][Kn];
    int wl = (threadIdx.x >> 5);

    for (int it = 0; it < Kn; it++) {
        // local argmax over live values (ascending j -> lowest index on tie)
        float best = -FLT_MAX; int bj = 0;
        #pragma unroll
        for (int j = 0; j < 64; j++) {
            float val = ((kill >> j) & 1ULL) ? -FLT_MAX : v[j];
            if (val > best) { best = val; bj = j; }
        }
        int bidx = bj * 32 + lane;

        // warp argmax (value desc, lower index on tie)
        #pragma unroll
        for (int o = 16; o; o >>= 1) {
            float ov = __shfl_xor_sync(0xffffffffu, best, o);
            int   oi = __shfl_xor_sync(0xffffffffu, bidx, o);
            if (ov > best || (ov == best && oi < bidx)) { best = ov; bidx = oi; }
        }

        if (lane == 0) { tv_s[wl][it] = best; ti_s[wl][it] = bidx; }
        if ((bidx & 31) == lane) kill |= 1ULL << (bidx >> 5);
    }
    __syncwarp();

    if (lane < Kn) {
        float mx = tv_s[wl][0];
        float sum = 0.f;
        #pragma unroll
        for (int i = 0; i < Kn; i++) sum += expf(tv_s[wl][i] - mx);
        g_w[warp * Kn + lane]   = expf(tv_s[wl][lane] - mx) / sum;
        g_idx[warp * Kn + lane] = ti_s[wl][lane];
    }
}

// ---------------------------------------------------------------------------
// Kernel 5: nei[m,:] = sum_k w[m,k] * A_sum[idx[m,k], :]
// ---------------------------------------------------------------------------
__global__ __launch_bounds__(256) void k_gather() {
    int m = blockIdx.x, tid = threadIdx.x;
    __shared__ float ws[Kn];
    __shared__ int   is[Kn];
    if (tid < Kn) { ws[tid] = g_w[m * Kn + tid]; is[tid] = g_idx[m * Kn + tid]; }
    __syncthreads();

    for (int c = tid; c < Nn / 4; c += 256) {
        float4 acc = make_float4(0.f, 0.f, 0.f, 0.f);
        #pragma unroll
        for (int k = 0; k < Kn; k++) {
            const float4 v = ((const float4*)(g_asum + (size_t)is[k] * Nn))[c];
            float wk = ws[k];
            acc.x += wk * v.x; acc.y += wk * v.y;
            acc.z += wk * v.z; acc.w += wk * v.w;
        }
        ((float4*)(g_nei + (size_t)m * Nn))[c] = acc;
    }
}

// ---------------------------------------------------------------------------
// Kernel 6: out = nei (256x2048) @ keys (2048x768)  [NN SGEMM, split-K,
// register double buffering].  Grid (12, 4, SPLITK) = 192 blocks.
// ---------------------------------------------------------------------------
__global__ __launch_bounds__(256) void k_out() {
    const int BM = 64, BN = 64, BK = 16;
    const int KC = Nn / SPLITK;   // 512
    __shared__ float As[BK][BM + 4];
    __shared__ float Bs[BK][BN + 4];

    int tid = threadIdx.x;
    int m0 = blockIdx.y * BM;
    int n0 = blockIdx.x * BN;
    int kbase = blockIdx.z * KC;

    int lr = tid >> 2;          // 0..63 (A row)
    int lk = (tid & 3) * 4;     // 0,4,8,12 (A k-offset)
    int br = tid >> 4;          // 0..15 (B k-row)
    int bc = (tid & 15) * 4;    // 0..60 (B col)
    int rm = (tid >> 4) * 4;
    int rn = (tid & 15) * 4;

    float acc[4][4];
    #pragma unroll
    for (int i = 0; i < 4; i++)
        #pragma unroll
        for (int j = 0; j < 4; j++) acc[i][j] = 0.f;

    // prologue
    float4 a = *(const float4*)&g_nei[(size_t)(m0 + lr) * Nn + kbase + lk];
    float4 b = *(const float4*)&g_keys[(size_t)(kbase + br) * Dn + n0 + bc];

    for (int kb = kbase; kb < kbase + KC; kb += BK) {
        As[lk + 0][lr] = a.x; As[lk + 1][lr] = a.y;
        As[lk + 2][lr] = a.z; As[lk + 3][lr] = a.w;
        *(float4*)&Bs[br][bc] = b;
        __syncthreads();

        if (kb + BK < kbase + KC) {
            a = *(const float4*)&g_nei[(size_t)(m0 + lr) * Nn + kb + BK + lk];
            b = *(const float4*)&g_keys[(size_t)(kb + BK + br) * Dn + n0 + bc];
        }

        #pragma unroll
        for (int kk = 0; kk < BK; kk++) {
            float4 ra = *(float4*)&As[kk][rm];
            float4 rb = *(float4*)&Bs[kk][rn];
            acc[0][0] += ra.x * rb.x; acc[0][1] += ra.x * rb.y;
            acc[0][2] += ra.x * rb.z; acc[0][3] += ra.x * rb.w;
            acc[1][0] += ra.y * rb.x; acc[1][1] += ra.y * rb.y;
            acc[1][2] += ra.y * rb.z; acc[1][3] += ra.y * rb.w;
            acc[2][0] += ra.z * rb.x; acc[2][1] += ra.z * rb.y;
            acc[2][2] += ra.z * rb.z; acc[2][3] += ra.z * rb.w;
            acc[3][0] += ra.w * rb.x; acc[3][1] += ra.w * rb.y;
            acc[3][2] += ra.w * rb.z; acc[3][3] += ra.w * rb.w;
        }
        __syncthreads();
    }

    float* P = g_outp[blockIdx.z];
    #pragma unroll
    for (int i = 0; i < 4; i++) {
        float4 v = make_float4(acc[i][0], acc[i][1], acc[i][2], acc[i][3]);
        *(float4*)&P[(size_t)(m0 + rm + i) * Dn + n0 + rn] = v;
    }
}

// ---------------------------------------------------------------------------
// Kernel 7: out = sum of SPLITK partials
// ---------------------------------------------------------------------------
__global__ __launch_bounds__(256) void k_reduce(float4* __restrict__ out) {
    int i = blockIdx.x * 256 + threadIdx.x;   // 0 .. Mn*Dn/4-1
    float4 r = ((const float4*)g_outp[0])[i];
    #pragma unroll
    for (int s = 1; s < SPLITK; s++) {
        float4 t = ((const float4*)g_outp[s])[i];
        r.x += t.x; r.y += t.y; r.z += t.z; r.w += t.w;
    }
    out[i] = r;
}

// ---------------------------------------------------------------------------
// Host launcher — default stream, graph-capturable.
// Inputs: positions, keys_param, adjacency, k (fixed 16).
// ---------------------------------------------------------------------------
extern "C" void kernel_launch(void* const* d_in, const int* in_sizes, int n_in,
                              void* d_out, int out_size) {
    (void)in_sizes; (void)n_in; (void)out_size;
    const float* positions = (const float*)d_in[0];
    const float* keys_p    = (const float*)d_in[1];
    const float* adjacency = (const float*)d_in[2];
    float* out = (float*)d_out;

    k_norm  <<<Nn, 256>>>(keys_p);
    k_asum  <<<(Nn * Nn / 4) / 256, 256>>>((const float4*)adjacency);
    k_scores<<<dim3(Nn / 64, Mn / 64), 256>>>(positions);
    k_topk  <<<Mn / 4, 128>>>();
    k_gather<<<Mn, 256>>>();
    k_out   <<<dim3(Dn / 64, Mn / 64, SPLITK), 256>>>();
    k_reduce<<<(Mn * Dn / 4) / 256, 256>>>((float4*)out);
}